// round 1
// baseline (speedup 1.0000x reference)
#include <cuda_runtime.h>
#include <math.h>

// ---------------- problem constants ----------------
#define SEQ   4096
#define HID   2048
#define NH    16
#define NKV   4
#define DH    128
#define BLKQ  64
#define NBLK  64
#define MSK   32
#define KTOP  8

#define NEGV  (-1000000000.0f)

// ---------------- scratch (device globals; no allocation allowed) ----------------
__device__ float g_q[SEQ * HID];            // roped q, layout [s][h*128+d]
__device__ float g_k[SEQ * (NKV * DH)];     // roped k, layout [s][kvh*128+d]
__device__ float g_v[SEQ * (NKV * DH)];     // v,       layout [s][kvh*128+d]
__device__ float g_attn[SEQ * HID];         // attention output [s][h*128+d]
__device__ float g_Sq[NH * NBLK * MSK];
__device__ float g_Sk[NKV * NBLK * MSK];
__device__ int   g_topk[NH * NBLK * KTOP];
__device__ float g_cos[SEQ * 64];
__device__ float g_sin[SEQ * 64];

// ---------------- SGEMM: C[M,N] = A[M,K] @ B[K,N], all row-major fp32 ----------------
// 128x128 tile, BK=16, 256 threads, 8x8 per thread (split 4+4 quads).
__global__ __launch_bounds__(256) void sgemm_kernel(
    const float* __restrict__ A, const float* __restrict__ B, float* __restrict__ C,
    int M, int N, int K)
{
    __shared__ float As[16][128];   // transposed A tile: As[k][m]
    __shared__ float Bs[16][128];   // B tile: Bs[k][n]

    int bx = blockIdx.x * 128;      // N offset
    int by = blockIdx.y * 128;      // M offset
    int t  = threadIdx.x;
    int ty = t >> 4;                // 0..15
    int tx = t & 15;                // 0..15

    float acc[8][8];
#pragma unroll
    for (int i = 0; i < 8; i++)
#pragma unroll
        for (int j = 0; j < 8; j++) acc[i][j] = 0.0f;

    for (int kt = 0; kt < K; kt += 16) {
        // load A tile 128x16 (transposed into As)
#pragma unroll
        for (int l = 0; l < 2; l++) {
            int lin = t + l * 256;
            int r   = lin >> 2;
            int c4  = (lin & 3) * 4;
            float4 a = *(const float4*)&A[(size_t)(by + r) * K + kt + c4];
            As[c4 + 0][r] = a.x;
            As[c4 + 1][r] = a.y;
            As[c4 + 2][r] = a.z;
            As[c4 + 3][r] = a.w;
        }
        // load B tile 16x128
#pragma unroll
        for (int l = 0; l < 2; l++) {
            int lin = t + l * 256;
            int r   = lin >> 5;
            int c4  = (lin & 31) * 4;
            *(float4*)&Bs[r][c4] = *(const float4*)&B[(size_t)(kt + r) * N + bx + c4];
        }
        __syncthreads();

#pragma unroll
        for (int k = 0; k < 16; k++) {
            float4 a0 = *(float4*)&As[k][ty * 4];
            float4 a1 = *(float4*)&As[k][64 + ty * 4];
            float4 b0 = *(float4*)&Bs[k][tx * 4];
            float4 b1 = *(float4*)&Bs[k][64 + tx * 4];
            float av[8] = {a0.x, a0.y, a0.z, a0.w, a1.x, a1.y, a1.z, a1.w};
            float bv[8] = {b0.x, b0.y, b0.z, b0.w, b1.x, b1.y, b1.z, b1.w};
#pragma unroll
            for (int i = 0; i < 8; i++)
#pragma unroll
                for (int j = 0; j < 8; j++)
                    acc[i][j] += av[i] * bv[j];
        }
        __syncthreads();
    }

#pragma unroll
    for (int i = 0; i < 8; i++) {
        int row = by + ((i < 4) ? (ty * 4 + i) : (64 + ty * 4 + i - 4));
        float4 c0 = make_float4(acc[i][0], acc[i][1], acc[i][2], acc[i][3]);
        float4 c1 = make_float4(acc[i][4], acc[i][5], acc[i][6], acc[i][7]);
        *(float4*)&C[(size_t)row * N + bx + tx * 4]      = c0;
        *(float4*)&C[(size_t)row * N + bx + 64 + tx * 4] = c1;
    }
}

// ---------------- RoPE cos/sin table (fp64 trig for accuracy, tiny cost) ----------------
__global__ void rope_table_kernel(const int* __restrict__ pos)
{
    int s = blockIdx.x;
    int j = threadIdx.x;  // 0..63
    double invf = exp(-((double)(2 * j) / 128.0) * log(10000.0));
    double ang  = (double)pos[s] * invf;
    double sv, cv;
    sincos(ang, &sv, &cv);
    g_cos[s * 64 + j] = (float)cv;
    g_sin[s * 64 + j] = (float)sv;
}

// ---------------- RoPE in place: grid (S, nheads), 128 threads ----------------
__global__ void rope_kernel(float* __restrict__ buf, int stride)
{
    int s = blockIdx.x;
    int h = blockIdx.y;
    int d = threadIdx.x;
    __shared__ float row[DH];
    float x = buf[(size_t)s * stride + h * DH + d];
    row[d] = x;
    __syncthreads();
    float part = (d < 64) ? -row[d + 64] : row[d - 64];
    float c  = g_cos[s * 64 + (d & 63)];
    float sn = g_sin[s * 64 + (d & 63)];
    buf[(size_t)s * stride + h * DH + d] = x * c + part * sn;
}

// ---------------- sketch: S[h][n][m] = mean_r( buf[n*64+r] ) @ H  ----------------
__global__ void sketch_kernel(const float* __restrict__ buf, const float* __restrict__ Hm,
                              float* __restrict__ Sout, int stride)
{
    int n = blockIdx.x;   // block index
    int h = blockIdx.y;   // head
    int d = threadIdx.x;  // 0..127
    __shared__ float mv[DH];
    float sum = 0.0f;
#pragma unroll 8
    for (int r = 0; r < BLKQ; r++)
        sum += buf[(size_t)(n * BLKQ + r) * stride + h * DH + d];
    mv[d] = sum * (1.0f / 64.0f);
    __syncthreads();
    if (d < MSK) {
        float acc = 0.0f;
#pragma unroll 8
        for (int dd = 0; dd < DH; dd++)
            acc += mv[dd] * Hm[dd * MSK + d];
        Sout[(h * NBLK + n) * MSK + d] = acc;
    }
}

// ---------------- block-score + top-k selection: grid (NBLK, NH), 64 threads ----------------
__global__ void topk_kernel()
{
    int i = blockIdx.x;   // query block
    int h = blockIdx.y;   // head
    int j = threadIdx.x;  // candidate key block
    __shared__ float bs[NBLK];

    float val;
    if (j > i) {
        val = NEGV;
    } else {
        const float* sq = &g_Sq[(h * NBLK + i) * MSK];
        const float* sk = &g_Sk[((h >> 2) * NBLK + j) * MSK];
        float acc = 0.0f;
#pragma unroll
        for (int m = 0; m < MSK; m++) acc += sq[m] * sk[m];
        val = acc;
    }
    if (j == i) val = 1000000000.0f;
    bs[j] = val;
    __syncthreads();

    if (j == 0) {
        // 8 passes of argmax, lowest index wins ties (matches jax.lax.top_k)
        for (int t = 0; t < KTOP; t++) {
            float best = -INFINITY;
            int bi = 0;
            for (int c = 0; c < NBLK; c++) {
                if (bs[c] > best) { best = bs[c]; bi = c; }
            }
            g_topk[(h * NBLK + i) * KTOP + t] = bi;
            bs[bi] = -INFINITY;
        }
    }
}

// ---------------- sparse flash attention: grid (NBLK, NH), 256 threads ----------------
// dynamic smem: QsT[128][65] + KVs[128][65] + Ps[64][65] + m/l/alpha[64 each]
#define ATT_SMEM_FLOATS (128 * 65 + 128 * 65 + 64 * 65 + 3 * 64)
#define ATT_SMEM_BYTES  (ATT_SMEM_FLOATS * 4)

__global__ __launch_bounds__(256) void attn_kernel()
{
    extern __shared__ float sm[];
    float* QsT = sm;                    // [dd][r]  stride 65
    float* KVs = QsT + 128 * 65;        // [dd][c]  stride 65 (K, then reused for V as [dcol][c])
    float* Ps  = KVs + 128 * 65;        // [r][c]   stride 65
    float* m_s = Ps + 64 * 65;
    float* l_s = m_s + 64;
    float* a_s = l_s + 64;

    int i   = blockIdx.x;    // query block
    int h   = blockIdx.y;    // head
    int kvh = h >> 2;
    int t   = threadIdx.x;
    int ty  = t >> 4;        // 0..15 -> rows ty*4..ty*4+3
    int tx  = t & 15;        // 0..15 -> cols tx*4.. and 64+tx*4..

    const float scale = 0.088388347648318447f;  // 1/sqrt(128)

    // load Q block, fold in scale
    for (int idx = t; idx < BLKQ * DH; idx += 256) {
        int r  = idx >> 7;
        int dd = idx & 127;
        QsT[dd * 65 + r] = g_q[(size_t)(i * BLKQ + r) * HID + h * DH + dd] * scale;
    }
    if (t < 64) { m_s[t] = -INFINITY; l_s[t] = 0.0f; }

    float O[4][8];
#pragma unroll
    for (int ii = 0; ii < 4; ii++)
#pragma unroll
        for (int jj = 0; jj < 8; jj++) O[ii][jj] = 0.0f;

    __syncthreads();

    for (int kb = 0; kb < KTOP; kb++) {
        int j = g_topk[(h * NBLK + i) * KTOP + kb];

        // load K block (transposed: KVs[dd][c])
        for (int idx = t; idx < BLKQ * DH; idx += 256) {
            int c  = idx >> 7;
            int dd = idx & 127;
            KVs[dd * 65 + c] = g_k[(size_t)(j * BLKQ + c) * (NKV * DH) + kvh * DH + dd];
        }
        __syncthreads();

        // scores: acc[4][4] = Q K^T (already scaled)
        float acc[4][4];
#pragma unroll
        for (int ii = 0; ii < 4; ii++)
#pragma unroll
            for (int jj = 0; jj < 4; jj++) acc[ii][jj] = 0.0f;

#pragma unroll 8
        for (int dd = 0; dd < DH; dd++) {
            float qv[4], kv[4];
#pragma unroll
            for (int ii = 0; ii < 4; ii++) qv[ii] = QsT[dd * 65 + ty * 4 + ii];
#pragma unroll
            for (int jj = 0; jj < 4; jj++) kv[jj] = KVs[dd * 65 + tx * 4 + jj];
#pragma unroll
            for (int ii = 0; ii < 4; ii++)
#pragma unroll
                for (int jj = 0; jj < 4; jj++) acc[ii][jj] += qv[ii] * kv[jj];
        }

        // mask (kpos <= qpos) and store to Ps
#pragma unroll
        for (int ii = 0; ii < 4; ii++) {
            int r = ty * 4 + ii;
            int qpos = i * BLKQ + r;
#pragma unroll
            for (int jj = 0; jj < 4; jj++) {
                int c = tx * 4 + jj;
                int kpos = j * BLKQ + c;
                Ps[r * 65 + c] = (kpos <= qpos) ? acc[ii][jj] : NEGV;
            }
        }
        __syncthreads();

        // online softmax per row (64 threads)
        if (t < 64) {
            int r = t;
            float rmax = -INFINITY;
#pragma unroll 8
            for (int c = 0; c < BLKQ; c++) rmax = fmaxf(rmax, Ps[r * 65 + c]);
            float mo = m_s[r];
            float mn = fmaxf(mo, rmax);
            float al = expf(mo - mn);
            float sum = 0.0f;
#pragma unroll 8
            for (int c = 0; c < BLKQ; c++) {
                float p = expf(Ps[r * 65 + c] - mn);
                Ps[r * 65 + c] = p;
                sum += p;
            }
            l_s[r] = l_s[r] * al + sum;
            m_s[r] = mn;
            a_s[r] = al;
        }
        __syncthreads();

        // rescale accumulator
        float alr[4];
#pragma unroll
        for (int ii = 0; ii < 4; ii++) alr[ii] = a_s[ty * 4 + ii];
#pragma unroll
        for (int ii = 0; ii < 4; ii++)
#pragma unroll
            for (int jj = 0; jj < 8; jj++) O[ii][jj] *= alr[ii];

        // load V block into same buffer (VsT[dcol][c])
        for (int idx = t; idx < BLKQ * DH; idx += 256) {
            int c    = idx >> 7;
            int dcol = idx & 127;
            KVs[dcol * 65 + c] = g_v[(size_t)(j * BLKQ + c) * (NKV * DH) + kvh * DH + dcol];
        }
        __syncthreads();

        // O += P @ V
#pragma unroll 4
        for (int c = 0; c < BLKQ; c++) {
            float pr[4];
#pragma unroll
            for (int ii = 0; ii < 4; ii++) pr[ii] = Ps[(ty * 4 + ii) * 65 + c];
            float pv[8];
#pragma unroll
            for (int jj = 0; jj < 4; jj++) {
                pv[jj]     = KVs[(tx * 4 + jj) * 65 + c];
                pv[4 + jj] = KVs[(64 + tx * 4 + jj) * 65 + c];
            }
#pragma unroll
            for (int ii = 0; ii < 4; ii++)
#pragma unroll
                for (int jj = 0; jj < 8; jj++) O[ii][jj] += pr[ii] * pv[jj];
        }
        __syncthreads();
    }

    // epilogue: divide by l, write out
    float linv[4];
#pragma unroll
    for (int ii = 0; ii < 4; ii++) linv[ii] = 1.0f / l_s[ty * 4 + ii];
#pragma unroll
    for (int ii = 0; ii < 4; ii++) {
        int r = i * BLKQ + ty * 4 + ii;
#pragma unroll
        for (int jj = 0; jj < 8; jj++) {
            int col = (jj < 4) ? (tx * 4 + jj) : (64 + tx * 4 + jj - 4);
            g_attn[(size_t)r * HID + h * DH + col] = O[ii][jj] * linv[ii];
        }
    }
}

// ---------------- launch ----------------
extern "C" void kernel_launch(void* const* d_in, const int* in_sizes, int n_in,
                              void* d_out, int out_size)
{
    const float* hs  = (const float*)d_in[0];
    const int*   pos = (const int*)d_in[1];
    const float* Wq  = (const float*)d_in[2];
    const float* Wk  = (const float*)d_in[3];
    const float* Wv  = (const float*)d_in[4];
    const float* Wo  = (const float*)d_in[5];
    const float* Hm  = (const float*)d_in[6];
    float* out = (float*)d_out;

    float *q, *k, *v, *attn, *Sq, *Sk;
    cudaGetSymbolAddress((void**)&q,    g_q);
    cudaGetSymbolAddress((void**)&k,    g_k);
    cudaGetSymbolAddress((void**)&v,    g_v);
    cudaGetSymbolAddress((void**)&attn, g_attn);
    cudaGetSymbolAddress((void**)&Sq,   g_Sq);
    cudaGetSymbolAddress((void**)&Sk,   g_Sk);

    // QKV projections
    sgemm_kernel<<<dim3(HID / 128, SEQ / 128), 256>>>(hs, Wq, q, SEQ, HID, HID);
    sgemm_kernel<<<dim3((NKV * DH) / 128, SEQ / 128), 256>>>(hs, Wk, k, SEQ, NKV * DH, HID);
    sgemm_kernel<<<dim3((NKV * DH) / 128, SEQ / 128), 256>>>(hs, Wv, v, SEQ, NKV * DH, HID);

    // RoPE
    rope_table_kernel<<<SEQ, 64>>>(pos);
    rope_kernel<<<dim3(SEQ, NH), DH>>>(q, HID);
    rope_kernel<<<dim3(SEQ, NKV), DH>>>(k, NKV * DH);

    // sketches
    sketch_kernel<<<dim3(NBLK, NH), DH>>>(q, Hm, Sq, HID);
    sketch_kernel<<<dim3(NBLK, NKV), DH>>>(k, Hm, Sk, NKV * DH);

    // block scores + top-k
    topk_kernel<<<dim3(NBLK, NH), 64>>>();

    // sparse attention
    cudaFuncSetAttribute(attn_kernel, cudaFuncAttributeMaxDynamicSharedMemorySize, ATT_SMEM_BYTES);
    attn_kernel<<<dim3(NBLK, NH), 256, ATT_SMEM_BYTES>>>();

    // output projection
    sgemm_kernel<<<dim3(HID / 128, SEQ / 128), 256>>>(attn, Wo, out, SEQ, HID, HID);
}